// round 8
// baseline (speedup 1.0000x reference)
#include <cuda_runtime.h>
#include <cuda_bf16.h>

#define B_   128
#define T_   1024
#define F_   64
#define H_   256
#define KTOT 320           // F + H
#define NCTA 128
#define NTHR 256

// ---------------- static device scratch (no runtime allocs) ----------------
__device__ float d_xT[T_ * F_ * B_];        // [t][f][b]       33.5 MB
__device__ float d_hist[T_ * H_ * B_];      // [s][j][b]      134.2 MB (decoder carry h)
__device__ float d_H[2 * H_ * B_];          // double-buffered h, [buf][j][b]
__device__ unsigned d_bar;                  // grid barrier counter

// ---------------- kernel 0: reset barrier + zero h0 ----------------
__global__ void init_kernel() {
    int i = blockIdx.x * blockDim.x + threadIdx.x;   // 128*256 = 32768 = H_*B_
    d_H[i] = 0.0f;                                   // buffer 0 = initial h = 0
    if (i == 0) d_bar = 0u;
}

// ---------------- kernel 1: transpose x to [t][f][b] ----------------
__global__ __launch_bounds__(NTHR) void transpose_kernel(const float* __restrict__ ts) {
    __shared__ float tile[F_][B_ + 1];
    int t = blockIdx.x;
    for (int idx = threadIdx.x; idx < B_ * F_; idx += NTHR) {
        int b = idx >> 6, f = idx & 63;
        tile[f][b] = ts[(size_t)b * (T_ * F_) + t * F_ + f];     // coalesced over f
    }
    __syncthreads();
    for (int idx = threadIdx.x; idx < F_ * B_; idx += NTHR) {
        int f = idx >> 7, b = idx & 127;
        d_xT[(size_t)t * (F_ * B_) + f * B_ + b] = tile[f][b];   // coalesced over b
    }
}

// ---------------- kernel 2: persistent LSTM (encoder + decoder) ----------------
// smem floats: A[320][32]=10240 | W[2][320][32]=20480 | stg[2][32][33]=2112
#define SM_A_OFF  0
#define SM_W_OFF  10240
#define SM_S_OFF  30720
#define SMEM_PERSIST_FLOATS (30720 + 2112)
#define SMEM_PERSIST_BYTES  (SMEM_PERSIST_FLOATS * 4)

__device__ __forceinline__ float sigf(float x) { return 1.0f / (1.0f + __expf(-x)); }

__global__ void __launch_bounds__(NTHR, 1) lstm_persistent(
    const float* __restrict__ Wih_e, const float* __restrict__ Whh_e, const float* __restrict__ b_e,
    const float* __restrict__ Wih_d, const float* __restrict__ Whh_d, const float* __restrict__ b_d)
{
    extern __shared__ float sm[];
    float* A    = sm + SM_A_OFF;
    float* W    = sm + SM_W_OFF;
    float* stg0 = sm + SM_S_OFF;            // group-0 partial gates [32][33]
    float* stg1 = stg0 + 32 * 33;           // group-1 partial gates [32][33]

    const int tid = threadIdx.x;
    const int cta = blockIdx.x;
    const int ms  = cta >> 5;          // 0..3  : 32-batch slice
    const int ns  = cta & 31;          // 0..31 : 8-hidden-unit slice
    const int m0  = ms * 32;

    // Split-K GEMM coords: group gid covers half of K; 16x8 threads, 2x4 tile
    const int gid  = tid >> 7;         // 0/1 : K-group
    const int half = tid & 127;
    const int tx   = half & 7;         // n-quad:  n0 = 4*tx
    const int ty   = half >> 3;        // m-pair:  mm = 2*ty
    const int k0   = gid * (KTOT / 2);
    const int k1   = k0 + (KTOT / 2);
    float* stgW = gid ? stg1 : stg0;

    // update/IO coords
    const int jl = tid >> 5;           // 0..7  local hidden unit
    const int mu = tid & 31;           // 0..31 local batch row
    const int jg = ns * 8 + jl;        // global hidden unit

    // ---- load both phases' weight slices into smem (once) ----
    // W[p][k][n]; column n -> gate g = n>>3, hidden j = ns*8 + (n&7); weight row = g*H + j
    for (int idx = tid; idx < 2 * KTOT * 32; idx += NTHR) {
        int p = idx / (KTOT * 32);
        int r = idx - p * (KTOT * 32);
        int k = r >> 5, n = r & 31;
        int row = (n >> 3) * H_ + (ns * 8 + (n & 7));
        const float* Wih = p ? Wih_d : Wih_e;
        const float* Whh = p ? Whh_d : Whh_e;
        W[idx] = (k < F_) ? Wih[row * F_ + k] : Whh[row * H_ + (k - F_)];
    }

    // biases for this thread's (jg): 4 gates x 2 phases
    const float bie = b_e[0 * H_ + jg], bfe = b_e[1 * H_ + jg],
                bge = b_e[2 * H_ + jg], boe = b_e[3 * H_ + jg];
    const float bid = b_d[0 * H_ + jg], bfd = b_d[1 * H_ + jg],
                bgd = b_d[2 * H_ + jg], bod = b_d[3 * H_ + jg];

    float c_reg = 0.0f;
    int cur = 0;
    __syncthreads();   // weights ready

    for (int step = 0; step < 2 * T_; ++step) {
        const bool dec = (step >= T_);
        const int  t   = dec ? (2 * T_ - 1 - step) : step;   // decoder consumes reversed x
        const float* Wp = W + (dec ? KTOT * 32 : 0);

        // ---- stage A = [x_t | h] for our 32 batch rows (float4 vectorized) ----
        {
            const float4* xsrc = (const float4*)(d_xT + (size_t)t * (F_ * B_) + m0);  // row stride B_/4
            const float4* hsrc = (const float4*)(d_H + cur * (H_ * B_) + m0);
            float4* Av = (float4*)A;
            #pragma unroll
            for (int i = tid; i < F_ * 8; i += NTHR) {          // x part: 64 rows x 8 float4
                int r = i >> 3, q = i & 7;
                Av[r * 8 + q] = __ldg(xsrc + r * (B_ / 4) + q);
            }
            #pragma unroll
            for (int i = tid; i < H_ * 8; i += NTHR) {          // h part: L2 only (coherence!)
                int r = i >> 3, q = i & 7;
                float4 v;
                const float* p = (const float*)(hsrc + r * (B_ / 4) + q);
                v.x = __ldcg(p + 0); v.y = __ldcg(p + 1);
                v.z = __ldcg(p + 2); v.w = __ldcg(p + 3);
                Av[(F_ + r) * 8 + q] = v;
            }
        }
        __syncthreads();

        // ---- 32x32x320 GEMM, split-K, 2x4 register tile ----
        float a00=0.f,a01=0.f,a02=0.f,a03=0.f,a10=0.f,a11=0.f,a12=0.f,a13=0.f;
        {
            const float* Ap = A + 2 * ty;
            const float* Bp = Wp + 4 * tx;
            #pragma unroll 10
            for (int k = k0; k < k1; ++k) {
                float2 av = *(const float2*)(Ap + k * 32);
                float4 bv = *(const float4*)(Bp + k * 32);
                a00 += av.x * bv.x; a01 += av.x * bv.y; a02 += av.x * bv.z; a03 += av.x * bv.w;
                a10 += av.y * bv.x; a11 += av.y * bv.y; a12 += av.y * bv.z; a13 += av.y * bv.w;
            }
        }
        {
            float* r0 = stgW + (2 * ty)     * 33 + 4 * tx;
            float* r1 = stgW + (2 * ty + 1) * 33 + 4 * tx;
            r0[0] = a00; r0[1] = a01; r0[2] = a02; r0[3] = a03;
            r1[0] = a10; r1[1] = a11; r1[2] = a12; r1[3] = a13;
        }
        __syncthreads();

        // ---- activations + cell update for our (mu, jl) ----
        float gi = stg0[mu * 33 +      jl] + stg1[mu * 33 +      jl] + (dec ? bid : bie);
        float gf = stg0[mu * 33 +  8 + jl] + stg1[mu * 33 +  8 + jl] + (dec ? bfd : bfe);
        float gg = stg0[mu * 33 + 16 + jl] + stg1[mu * 33 + 16 + jl] + (dec ? bgd : bge);
        float go = stg0[mu * 33 + 24 + jl] + stg1[mu * 33 + 24 + jl] + (dec ? bod : boe);
        gi = sigf(gi); gf = sigf(gf); go = sigf(go);
        gg = tanhf(gg);
        c_reg = gf * c_reg + gi * gg;
        float h = go * tanhf(c_reg);

        const int nxt = cur ^ 1;
        __stcg(d_H + nxt * (H_ * B_) + jg * B_ + m0 + mu, h);

        // decoder-carry history: hist[0] = encoder-final h; hist[s] = carry at decoder step s
        if (step >= T_ - 1 && step < 2 * T_ - 1) {
            int s = step - (T_ - 1);
            d_hist[(size_t)s * (H_ * B_) + jg * B_ + m0 + mu] = h;
        }

        // ---- grid barrier (release h writes, acquire others') ----
        __threadfence();
        __syncthreads();
        if (tid == 0) {
            atomicAdd(&d_bar, 1u);
            const unsigned target = (unsigned)(step + 1) * NCTA;
            while (*((volatile unsigned*)&d_bar) < target) { __nanosleep(64); }
        }
        __syncthreads();
        __threadfence();
        cur = nxt;
    }
}

// ---------------- kernel 3: output projection ----------------
// out[b][t][f] = sum_j hist[T-1-t][j][b] * W_out[f][j] + b_out[f]
#define SMEM_PROJ_BYTES ((H_ * F_ + F_) * 4)

__global__ void __launch_bounds__(256) proj_kernel(
    const float* __restrict__ Wout, const float* __restrict__ bout, float* __restrict__ out)
{
    extern __shared__ float sm[];
    float* Ws = sm;              // [j][f] transposed W_out
    float* bs = sm + H_ * F_;

    const int t = blockIdx.x;
    const int s = T_ - 1 - t;
    for (int i = threadIdx.x; i < H_ * F_; i += 256) {
        int j = i >> 6, f = i & 63;
        Ws[i] = Wout[f * H_ + j];
    }
    if (threadIdx.x < F_) bs[threadIdx.x] = bout[threadIdx.x];
    __syncthreads();

    const int b  = threadIdx.x & 127;
    const int fg = (threadIdx.x >> 7) * 32;     // f-group: 0 or 32

    float acc[32];
    #pragma unroll
    for (int f = 0; f < 32; ++f) acc[f] = bs[fg + f];

    const float* hrow = d_hist + (size_t)s * (H_ * B_) + b;
    #pragma unroll 4
    for (int j = 0; j < H_; ++j) {
        float hv = hrow[(size_t)j * B_];
        const float* wr = Ws + j * F_ + fg;
        #pragma unroll
        for (int f = 0; f < 32; ++f) acc[f] += hv * wr[f];
    }

    float* orow = out + (size_t)b * (T_ * F_) + t * F_ + fg;
    #pragma unroll
    for (int f = 0; f < 32; ++f) orow[f] = acc[f];
}

// ---------------- launch ----------------
extern "C" void kernel_launch(void* const* d_in, const int* in_sizes, int n_in,
                              void* d_out, int out_size) {
    const float* ts    = (const float*)d_in[0];
    const float* Wih_e = (const float*)d_in[1];
    const float* Whh_e = (const float*)d_in[2];
    const float* b_e   = (const float*)d_in[3];
    const float* Wih_d = (const float*)d_in[4];
    const float* Whh_d = (const float*)d_in[5];
    const float* b_d   = (const float*)d_in[6];
    const float* Wout  = (const float*)d_in[7];
    const float* bout  = (const float*)d_in[8];
    float* out = (float*)d_out;

    cudaFuncSetAttribute(lstm_persistent, cudaFuncAttributeMaxDynamicSharedMemorySize,
                         SMEM_PERSIST_BYTES);
    cudaFuncSetAttribute(proj_kernel, cudaFuncAttributeMaxDynamicSharedMemorySize,
                         SMEM_PROJ_BYTES);

    init_kernel<<<128, 256>>>();
    transpose_kernel<<<T_, NTHR>>>(ts);
    lstm_persistent<<<NCTA, NTHR, SMEM_PERSIST_BYTES>>>(Wih_e, Whh_e, b_e,
                                                        Wih_d, Whh_d, b_d);
    proj_kernel<<<T_, 256, SMEM_PROJ_BYTES>>>(Wout, bout, out);
}

// round 9
// speedup vs baseline: 1.0388x; 1.0388x over previous
#include <cuda_runtime.h>
#include <cuda_bf16.h>

#define B_   128
#define T_   1024
#define F_   64
#define H_   256
#define KTOT 320           // F + H
#define NCTA 128
#define NTHR 256

typedef unsigned long long u64;

// ---------------- packed f32x2 helpers (sm_103a FFMA2 path) ----------------
__device__ __forceinline__ u64 pack2(float x, float y) {
    u64 r; asm("mov.b64 %0, {%1,%2};" : "=l"(r) : "f"(x), "f"(y)); return r;
}
__device__ __forceinline__ void fma2(u64& d, u64 a, u64 b) {
    asm("fma.rn.f32x2 %0, %1, %2, %0;" : "+l"(d) : "l"(a), "l"(b));
}
__device__ __forceinline__ void unpack2(float& x, float& y, u64 v) {
    asm("mov.b64 {%0,%1}, %2;" : "=f"(x), "=f"(y) : "l"(v));
}

// ---------------- static device scratch (no runtime allocs) ----------------
__device__ float d_xT[T_ * F_ * B_];        // [t][f][b]       33.5 MB
__device__ float d_hist[T_ * H_ * B_];      // [s][j][b]      134.2 MB (decoder carry h)
__device__ float d_H[2 * H_ * B_];          // double-buffered h, [buf][j][b]
__device__ unsigned d_bar;                  // grid barrier counter

// ---------------- kernel 0: reset barrier + zero h0 ----------------
__global__ void init_kernel() {
    int i = blockIdx.x * blockDim.x + threadIdx.x;   // 128*256 = 32768 = H_*B_
    d_H[i] = 0.0f;                                   // buffer 0 = initial h = 0
    if (i == 0) d_bar = 0u;
}

// ---------------- kernel 1: transpose x to [t][f][b] ----------------
__global__ __launch_bounds__(NTHR) void transpose_kernel(const float* __restrict__ ts) {
    __shared__ float tile[F_][B_ + 1];
    int t = blockIdx.x;
    for (int idx = threadIdx.x; idx < B_ * F_; idx += NTHR) {
        int b = idx >> 6, f = idx & 63;
        tile[f][b] = ts[(size_t)b * (T_ * F_) + t * F_ + f];     // coalesced over f
    }
    __syncthreads();
    for (int idx = threadIdx.x; idx < F_ * B_; idx += NTHR) {
        int f = idx >> 7, b = idx & 127;
        d_xT[(size_t)t * (F_ * B_) + f * B_ + b] = tile[f][b];   // coalesced over b
    }
}

// ---------------- kernel 2: persistent LSTM (encoder + decoder) ----------------
// smem floats: A[320][32]=10240 | W[2][320][32]=20480 | stg[2][32][33]=2112
#define SM_A_OFF  0
#define SM_W_OFF  10240
#define SM_S_OFF  30720
#define SMEM_PERSIST_FLOATS (30720 + 2112)
#define SMEM_PERSIST_BYTES  (SMEM_PERSIST_FLOATS * 4)

__device__ __forceinline__ float sigf(float x) { return 1.0f / (1.0f + __expf(-x)); }

__global__ void __launch_bounds__(NTHR, 1) lstm_persistent(
    const float* __restrict__ Wih_e, const float* __restrict__ Whh_e, const float* __restrict__ b_e,
    const float* __restrict__ Wih_d, const float* __restrict__ Whh_d, const float* __restrict__ b_d)
{
    extern __shared__ float sm[];
    float* A    = sm + SM_A_OFF;
    float* W    = sm + SM_W_OFF;
    float* stg0 = sm + SM_S_OFF;            // group-0 partial gates [32][33]
    float* stg1 = stg0 + 32 * 33;           // group-1 partial gates [32][33]

    const int tid = threadIdx.x;
    const int cta = blockIdx.x;
    const int ms  = cta >> 5;          // 0..3  : 32-batch slice
    const int ns  = cta & 31;          // 0..31 : 8-hidden-unit slice
    const int m0  = ms * 32;

    // Split-K GEMM coords: group gid covers half of K; 16x8 threads, 2x4 tile
    const int gid  = tid >> 7;         // 0/1 : K-group
    const int half = tid & 127;
    const int tx   = half & 7;         // n-quad:  n0 = 4*tx
    const int ty   = half >> 3;        // m-pair:  mm = 2*ty
    const int k0   = gid * (KTOT / 2);
    const int k1   = k0 + (KTOT / 2);
    float* stgW = gid ? stg1 : stg0;

    // update/IO coords
    const int jl = tid >> 5;           // 0..7  local hidden unit
    const int mu = tid & 31;           // 0..31 local batch row
    const int jg = ns * 8 + jl;        // global hidden unit

    // ---- load both phases' weight slices into smem (once) ----
    // W[p][k][n]; column n -> gate g = n>>3, hidden j = ns*8 + (n&7); weight row = g*H + j
    for (int idx = tid; idx < 2 * KTOT * 32; idx += NTHR) {
        int p = idx / (KTOT * 32);
        int r = idx - p * (KTOT * 32);
        int k = r >> 5, n = r & 31;
        int row = (n >> 3) * H_ + (ns * 8 + (n & 7));
        const float* Wih = p ? Wih_d : Wih_e;
        const float* Whh = p ? Whh_d : Whh_e;
        W[idx] = (k < F_) ? Wih[row * F_ + k] : Whh[row * H_ + (k - F_)];
    }

    // biases for this thread's (jg): 4 gates x 2 phases
    const float bie = b_e[0 * H_ + jg], bfe = b_e[1 * H_ + jg],
                bge = b_e[2 * H_ + jg], boe = b_e[3 * H_ + jg];
    const float bid = b_d[0 * H_ + jg], bfd = b_d[1 * H_ + jg],
                bgd = b_d[2 * H_ + jg], bod = b_d[3 * H_ + jg];

    float4* Av = (float4*)A;

    // ---- prologue: stage x for step 0 (t = 0) ----
    {
        const float4* xsrc = (const float4*)(d_xT + m0);   // t = 0
        #pragma unroll
        for (int u = 0; u < 2; ++u) {
            int i = tid + u * NTHR;                         // i in [0, 512)
            int r = i >> 3, q = i & 7;
            Av[r * 8 + q] = __ldg(xsrc + r * (B_ / 4) + q);
        }
    }

    float c_reg = 0.0f;
    int cur = 0;
    __syncthreads();   // weights + x0 ready (h staged in loop)

    for (int step = 0; step < 2 * T_; ++step) {
        const bool dec = (step >= T_);
        const float* Wp = W + (dec ? KTOT * 32 : 0);

        // ---- stage h (cur buffer) for our 32 batch rows: float4 L2 loads ----
        {
            const float4* hsrc = (const float4*)(d_H + cur * (H_ * B_) + m0);
            #pragma unroll
            for (int i = tid; i < H_ * 8; i += NTHR) {     // 2048 float4
                int r = i >> 3, q = i & 7;
                Av[(F_ + r) * 8 + q] = __ldcg(hsrc + r * (B_ / 4) + q);
            }
        }
        __syncthreads();

        // ---- 32x32x320 GEMM, split-K, 2x4 tile via packed fma.rn.f32x2 ----
        u64 c00 = 0ull, c01 = 0ull, c10 = 0ull, c11 = 0ull;
        {
            const float* Ap = A + 2 * ty;
            const float* Bp = Wp + 4 * tx;
            #pragma unroll 8
            for (int k = k0; k < k1; ++k) {
                float2 av = *(const float2*)(Ap + k * 32);
                ulonglong2 bb = *(const ulonglong2*)(Bp + k * 32);   // (b0,b1),(b2,b3)
                u64 a0 = pack2(av.x, av.x);
                u64 a1 = pack2(av.y, av.y);
                fma2(c00, a0, bb.x); fma2(c01, a0, bb.y);
                fma2(c10, a1, bb.x); fma2(c11, a1, bb.y);
            }
        }

        // ---- prefetch next step's x into registers (overlaps update+barrier) ----
        float4 xr0, xr1;
        const bool hasnext = (step + 1 < 2 * T_);
        if (hasnext) {
            const int sn = step + 1;
            const int tn = (sn >= T_) ? (2 * T_ - 1 - sn) : sn;
            const float4* xs2 = (const float4*)(d_xT + (size_t)tn * (F_ * B_) + m0);
            { int i = tid;        int r = i >> 3, q = i & 7; xr0 = __ldg(xs2 + r * (B_ / 4) + q); }
            { int i = tid + NTHR; int r = i >> 3, q = i & 7; xr1 = __ldg(xs2 + r * (B_ / 4) + q); }
        }

        // ---- write gate partials ----
        {
            float v0, v1, v2, v3;
            float* r0 = stgW + (2 * ty)     * 33 + 4 * tx;
            float* r1 = stgW + (2 * ty + 1) * 33 + 4 * tx;
            unpack2(v0, v1, c00); unpack2(v2, v3, c01);
            r0[0] = v0; r0[1] = v1; r0[2] = v2; r0[3] = v3;
            unpack2(v0, v1, c10); unpack2(v2, v3, c11);
            r1[0] = v0; r1[1] = v1; r1[2] = v2; r1[3] = v3;
        }
        __syncthreads();

        // ---- activations + cell update for our (mu, jl) ----
        float gi = stg0[mu * 33 +      jl] + stg1[mu * 33 +      jl] + (dec ? bid : bie);
        float gf = stg0[mu * 33 +  8 + jl] + stg1[mu * 33 +  8 + jl] + (dec ? bfd : bfe);
        float gg = stg0[mu * 33 + 16 + jl] + stg1[mu * 33 + 16 + jl] + (dec ? bgd : bge);
        float go = stg0[mu * 33 + 24 + jl] + stg1[mu * 33 + 24 + jl] + (dec ? bod : boe);
        gi = sigf(gi); gf = sigf(gf); go = sigf(go);
        gg = tanhf(gg);
        c_reg = gf * c_reg + gi * gg;
        float h = go * tanhf(c_reg);

        const int nxt = cur ^ 1;
        __stcg(d_H + nxt * (H_ * B_) + jg * B_ + m0 + mu, h);

        // decoder-carry history: hist[0] = encoder-final h; hist[s] = carry at decoder step s
        if (step >= T_ - 1 && step < 2 * T_ - 1) {
            int s = step - (T_ - 1);
            d_hist[(size_t)s * (H_ * B_) + jg * B_ + m0 + mu] = h;
        }

        // ---- store prefetched x into smem (A x-region free after GEMM sync) ----
        if (hasnext) {
            { int i = tid;        int r = i >> 3, q = i & 7; Av[r * 8 + q] = xr0; }
            { int i = tid + NTHR; int r = i >> 3, q = i & 7; Av[r * 8 + q] = xr1; }
        }

        // ---- grid barrier (release h writes, acquire others') ----
        __threadfence();
        __syncthreads();
        if (tid == 0) {
            atomicAdd(&d_bar, 1u);
            const unsigned target = (unsigned)(step + 1) * NCTA;
            while (*((volatile unsigned*)&d_bar) < target) { }
        }
        __syncthreads();
        __threadfence();
        cur = nxt;
    }
}

// ---------------- kernel 3: output projection (f32x2) ----------------
// out[b][t][f] = sum_j hist[T-1-t][j][b] * W_out[f][j] + b_out[f]
#define SMEM_PROJ_BYTES ((H_ * F_ + F_) * 4)

__global__ void __launch_bounds__(256) proj_kernel(
    const float* __restrict__ Wout, const float* __restrict__ bout, float* __restrict__ out)
{
    extern __shared__ float sm[];
    float* Ws = sm;              // [j][f] transposed W_out
    float* bs = sm + H_ * F_;

    const int t = blockIdx.x;
    const int s = T_ - 1 - t;
    for (int i = threadIdx.x; i < H_ * F_; i += 256) {
        int j = i >> 6, f = i & 63;
        Ws[i] = Wout[f * H_ + j];
    }
    if (threadIdx.x < F_) bs[threadIdx.x] = bout[threadIdx.x];
    __syncthreads();

    const int b  = threadIdx.x & 127;
    const int fg = (threadIdx.x >> 7) * 32;     // f-group: 0 or 32

    u64 acc[16];                                // pairs (fg+2i, fg+2i+1)
    #pragma unroll
    for (int i = 0; i < 16; ++i) acc[i] = pack2(bs[fg + 2 * i], bs[fg + 2 * i + 1]);

    const float* hrow = d_hist + (size_t)s * (H_ * B_) + b;
    #pragma unroll 4
    for (int j = 0; j < H_; ++j) {
        float hv = hrow[(size_t)j * B_];
        u64 hh = pack2(hv, hv);
        const ulonglong2* wr = (const ulonglong2*)(Ws + j * F_ + fg);
        #pragma unroll
        for (int i = 0; i < 8; ++i) {
            ulonglong2 wv = wr[i];
            fma2(acc[2 * i],     hh, wv.x);
            fma2(acc[2 * i + 1], hh, wv.y);
        }
    }

    float* orow = out + (size_t)b * (T_ * F_) + t * F_ + fg;
    #pragma unroll
    for (int i = 0; i < 16; ++i) {
        float lo, hi; unpack2(lo, hi, acc[i]);
        *(float2*)(orow + 2 * i) = make_float2(lo, hi);
    }
}

// ---------------- launch ----------------
extern "C" void kernel_launch(void* const* d_in, const int* in_sizes, int n_in,
                              void* d_out, int out_size) {
    const float* ts    = (const float*)d_in[0];
    const float* Wih_e = (const float*)d_in[1];
    const float* Whh_e = (const float*)d_in[2];
    const float* b_e   = (const float*)d_in[3];
    const float* Wih_d = (const float*)d_in[4];
    const float* Whh_d = (const float*)d_in[5];
    const float* b_d   = (const float*)d_in[6];
    const float* Wout  = (const float*)d_in[7];
    const float* bout  = (const float*)d_in[8];
    float* out = (float*)d_out;

    cudaFuncSetAttribute(lstm_persistent, cudaFuncAttributeMaxDynamicSharedMemorySize,
                         SMEM_PERSIST_BYTES);
    cudaFuncSetAttribute(proj_kernel, cudaFuncAttributeMaxDynamicSharedMemorySize,
                         SMEM_PROJ_BYTES);

    init_kernel<<<128, 256>>>();
    transpose_kernel<<<T_, NTHR>>>(ts);
    lstm_persistent<<<NCTA, NTHR, SMEM_PERSIST_BYTES>>>(Wih_e, Whh_e, b_e,
                                                        Wih_d, Whh_d, b_d);
    proj_kernel<<<T_, 256, SMEM_PROJ_BYTES>>>(Wout, bout, out);
}

// round 11
// speedup vs baseline: 1.1953x; 1.1507x over previous
#include <cuda_runtime.h>
#include <cuda_bf16.h>

#define B_   128
#define T_   1024
#define F_   64
#define H_   256
#define KTOT 320           // F + H
#define NCTA 128
#define NTHR 256

typedef unsigned long long u64;

// ---------------- packed f32x2 helpers (sm_103a FFMA2 path) ----------------
__device__ __forceinline__ u64 pack2(float x, float y) {
    u64 r; asm("mov.b64 %0, {%1,%2};" : "=l"(r) : "f"(x), "f"(y)); return r;
}
__device__ __forceinline__ void fma2(u64& d, u64 a, u64 b) {
    asm("fma.rn.f32x2 %0, %1, %2, %0;" : "+l"(d) : "l"(a), "l"(b));
}
__device__ __forceinline__ void unpack2(float& x, float& y, u64 v) {
    asm("mov.b64 {%0,%1}, %2;" : "=f"(x), "=f"(y) : "l"(v));
}

// ---------------- static device scratch (no runtime allocs) ----------------
__device__ float d_xT[T_ * F_ * B_];        // [t][f][b]       33.5 MB
__device__ float d_hist[T_ * H_ * B_];      // [s][j][b]      134.2 MB (decoder carry h)
__device__ float d_H[2 * H_ * B_];          // double-buffered h, [buf][j][b]
__device__ unsigned d_bar4[128];            // 4 group-barrier counters at stride 32 (128B)

// ---------------- kernel 0: reset barriers + zero h0 ----------------
__global__ void init_kernel() {
    int i = blockIdx.x * blockDim.x + threadIdx.x;   // 32768 = H_*B_
    d_H[i] = 0.0f;                                   // buffer 0 = initial h = 0
    if (i < 128) d_bar4[i] = 0u;
}

// ---------------- kernel 1: transpose x to [t][f][b] ----------------
__global__ __launch_bounds__(NTHR) void transpose_kernel(const float* __restrict__ ts) {
    __shared__ float tile[F_][B_ + 1];
    int t = blockIdx.x;
    for (int idx = threadIdx.x; idx < B_ * F_; idx += NTHR) {
        int b = idx >> 6, f = idx & 63;
        tile[f][b] = ts[(size_t)b * (T_ * F_) + t * F_ + f];     // coalesced over f
    }
    __syncthreads();
    for (int idx = threadIdx.x; idx < F_ * B_; idx += NTHR) {
        int f = idx >> 7, b = idx & 127;
        d_xT[(size_t)t * (F_ * B_) + f * B_ + b] = tile[f][b];   // coalesced over b
    }
}

// ---------------- kernel 2: persistent LSTM (encoder + decoder) ----------------
// smem floats: A[320][32]=10240 | W[2][320][32]=20480 | stg[2][32][33]=2112
#define SM_A_OFF  0
#define SM_W_OFF  10240
#define SM_S_OFF  30720
#define SMEM_PERSIST_FLOATS (30720 + 2112)
#define SMEM_PERSIST_BYTES  (SMEM_PERSIST_FLOATS * 4)

__device__ __forceinline__ float sigf(float x) { return 1.0f / (1.0f + __expf(-x)); }

__global__ void __launch_bounds__(NTHR, 1) lstm_persistent(
    const float* __restrict__ Wih_e, const float* __restrict__ Whh_e, const float* __restrict__ b_e,
    const float* __restrict__ Wih_d, const float* __restrict__ Whh_d, const float* __restrict__ b_d)
{
    extern __shared__ float sm[];
    float* A    = sm + SM_A_OFF;
    float* W    = sm + SM_W_OFF;
    float* stg0 = sm + SM_S_OFF;            // group-0 partial gates [32][33]
    float* stg1 = stg0 + 32 * 33;           // group-1 partial gates [32][33]

    const int tid = threadIdx.x;
    const int cta = blockIdx.x;
    const int ms  = cta >> 5;          // 0..3  : 32-batch slice (independent barrier group)
    const int ns  = cta & 31;          // 0..31 : 8-hidden-unit slice
    const int m0  = ms * 32;
    unsigned* barp = &d_bar4[ms * 32]; // this group's counter (own 128B line)

    // Split-K GEMM coords: 16x8 thread grid per group, 2x4 register tile
    const int gid  = tid >> 7;         // 0/1 : K-group
    const int half = tid & 127;
    const int tx   = half & 7;         // n-quad:  n0 = 4*tx
    const int ty   = half >> 3;        // m-pair:  mm = 2*ty
    const int xk0  = gid * 32;         // x-part: 32 k each
    const int hk0  = F_ + gid * 128;   // h-part: 128 k each
    float* stgW = gid ? stg1 : stg0;

    // update/IO coords
    const int jl = tid >> 5;           // 0..7  local hidden unit
    const int mu = tid & 31;           // 0..31 local batch row
    const int jg = ns * 8 + jl;        // global hidden unit

    // ---- load both phases' weight slices into smem (once) ----
    // W[p][k][n]; column n -> gate g = n>>3, hidden j = ns*8 + (n&7); weight row = g*H + j
    for (int idx = tid; idx < 2 * KTOT * 32; idx += NTHR) {
        int p = idx / (KTOT * 32);
        int r = idx - p * (KTOT * 32);
        int k = r >> 5, n = r & 31;
        int row = (n >> 3) * H_ + (ns * 8 + (n & 7));
        const float* Wih = p ? Wih_d : Wih_e;
        const float* Whh = p ? Whh_d : Whh_e;
        W[idx] = (k < F_) ? Wih[row * F_ + k] : Whh[row * H_ + (k - F_)];
    }

    // biases for this thread's (jg): 4 gates x 2 phases
    const float bie = b_e[0 * H_ + jg], bfe = b_e[1 * H_ + jg],
                bge = b_e[2 * H_ + jg], boe = b_e[3 * H_ + jg];
    const float bid = b_d[0 * H_ + jg], bfd = b_d[1 * H_ + jg],
                bgd = b_d[2 * H_ + jg], bod = b_d[3 * H_ + jg];

    float4* Av = (float4*)A;

    // ---- prologue: stage x for step 0 (t = 0) ----
    {
        const float4* xsrc = (const float4*)(d_xT + m0);   // t = 0
        #pragma unroll
        for (int u = 0; u < 2; ++u) {
            int i = tid + u * NTHR;                         // i in [0, 512)
            int r = i >> 3, q = i & 7;
            Av[r * 8 + q] = __ldg(xsrc + r * (B_ / 4) + q);
        }
    }

    float c_reg = 0.0f;
    int cur = 0;
    __syncthreads();   // weights + x0 ready

    for (int step = 0; step < 2 * T_; ++step) {
        const bool dec = (step >= T_);
        const float* Wp = W + (dec ? KTOT * 32 : 0);

        // ---- issue h loads into registers (latency overlapped by x-part GEMM) ----
        float4 hreg[8];
        {
            const float4* hsrc = (const float4*)(d_H + cur * (H_ * B_) + m0);
            #pragma unroll
            for (int u = 0; u < 8; ++u) {
                int i = tid + u * NTHR;
                int r = i >> 3, q = i & 7;
                hreg[u] = __ldcg(hsrc + r * (B_ / 4) + q);
            }
        }

        // ---- x-part GEMM (32 k from smem, staged last step) ----
        u64 c00 = 0ull, c01 = 0ull, c10 = 0ull, c11 = 0ull;
        const float* Ap = A + 2 * ty;
        const float* Bp = Wp + 4 * tx;
        #pragma unroll 8
        for (int kk = 0; kk < 32; ++kk) {
            int k = xk0 + kk;
            float2 av = *(const float2*)(Ap + k * 32);
            ulonglong2 bb = *(const ulonglong2*)(Bp + k * 32);
            u64 a0 = pack2(av.x, av.x);
            u64 a1 = pack2(av.y, av.y);
            fma2(c00, a0, bb.x); fma2(c01, a0, bb.y);
            fma2(c10, a1, bb.x); fma2(c11, a1, bb.y);
        }

        // ---- store h into smem A ----
        #pragma unroll
        for (int u = 0; u < 8; ++u) {
            int i = tid + u * NTHR;
            int r = i >> 3, q = i & 7;
            Av[(F_ + r) * 8 + q] = hreg[u];
        }
        __syncthreads();

        // ---- h-part GEMM (128 k) ----
        #pragma unroll 8
        for (int kk = 0; kk < 128; ++kk) {
            int k = hk0 + kk;
            float2 av = *(const float2*)(Ap + k * 32);
            ulonglong2 bb = *(const ulonglong2*)(Bp + k * 32);
            u64 a0 = pack2(av.x, av.x);
            u64 a1 = pack2(av.y, av.y);
            fma2(c00, a0, bb.x); fma2(c01, a0, bb.y);
            fma2(c10, a1, bb.x); fma2(c11, a1, bb.y);
        }

        // ---- prefetch next step's x into registers (overlaps update+barrier) ----
        float4 xr0, xr1;
        const bool hasnext = (step + 1 < 2 * T_);
        if (hasnext) {
            const int sn = step + 1;
            const int tn = (sn >= T_) ? (2 * T_ - 1 - sn) : sn;
            const float4* xs2 = (const float4*)(d_xT + (size_t)tn * (F_ * B_) + m0);
            { int i = tid;        int r = i >> 3, q = i & 7; xr0 = __ldg(xs2 + r * (B_ / 4) + q); }
            { int i = tid + NTHR; int r = i >> 3, q = i & 7; xr1 = __ldg(xs2 + r * (B_ / 4) + q); }
        }

        // ---- write gate partials ----
        {
            float v0, v1, v2, v3;
            float* r0 = stgW + (2 * ty)     * 33 + 4 * tx;
            float* r1 = stgW + (2 * ty + 1) * 33 + 4 * tx;
            unpack2(v0, v1, c00); unpack2(v2, v3, c01);
            r0[0] = v0; r0[1] = v1; r0[2] = v2; r0[3] = v3;
            unpack2(v0, v1, c10); unpack2(v2, v3, c11);
            r1[0] = v0; r1[1] = v1; r1[2] = v2; r1[3] = v3;
        }
        __syncthreads();

        // ---- activations + cell update for our (mu, jl) ----
        float gi = stg0[mu * 33 +      jl] + stg1[mu * 33 +      jl] + (dec ? bid : bie);
        float gf = stg0[mu * 33 +  8 + jl] + stg1[mu * 33 +  8 + jl] + (dec ? bfd : bfe);
        float gg = stg0[mu * 33 + 16 + jl] + stg1[mu * 33 + 16 + jl] + (dec ? bgd : bge);
        float go = stg0[mu * 33 + 24 + jl] + stg1[mu * 33 + 24 + jl] + (dec ? bod : boe);
        gi = sigf(gi); gf = sigf(gf); go = sigf(go);
        gg = tanhf(gg);
        c_reg = gf * c_reg + gi * gg;
        float h = go * tanhf(c_reg);

        const int nxt = cur ^ 1;
        __stcg(d_H + nxt * (H_ * B_) + jg * B_ + m0 + mu, h);

        // decoder-carry history: hist[0] = encoder-final h; hist[s] = carry at decoder step s
        if (step >= T_ - 1 && step < 2 * T_ - 1) {
            int s = step - (T_ - 1);
            d_hist[(size_t)s * (H_ * B_) + jg * B_ + m0 + mu] = h;
        }

        // ---- store prefetched x into smem (x rows free: only read pre-mid-sync) ----
        if (hasnext) {
            { int i = tid;        int r = i >> 3, q = i & 7; Av[r * 8 + q] = xr0; }
            { int i = tid + NTHR; int r = i >> 3, q = i & 7; Av[r * 8 + q] = xr1; }
        }

        // ---- group barrier (32 CTAs sharing ms): release/acquire, no membar.gl ----
        __syncthreads();
        if (tid == 0) {
            asm volatile("red.release.gpu.global.add.u32 [%0], 1;"
                         :: "l"(barp) : "memory");
            const unsigned target = (unsigned)(step + 1) * 32u;
            unsigned v;
            do {
                asm volatile("ld.acquire.gpu.global.u32 %0, [%1];"
                             : "=r"(v) : "l"(barp) : "memory");
            } while (v < target);
        }
        __syncthreads();
        cur = nxt;
    }
}

// ---------------- kernel 3: output projection (f32x2) ----------------
// out[b][t][f] = sum_j hist[T-1-t][j][b] * W_out[f][j] + b_out[f]
#define SMEM_PROJ_BYTES ((H_ * F_ + F_) * 4)

__global__ void __launch_bounds__(256) proj_kernel(
    const float* __restrict__ Wout, const float* __restrict__ bout, float* __restrict__ out)
{
    extern __shared__ float sm[];
    float* Ws = sm;              // [j][f] transposed W_out
    float* bs = sm + H_ * F_;

    const int t = blockIdx.x;
    const int s = T_ - 1 - t;
    for (int i = threadIdx.x; i < H_ * F_; i += 256) {
        int j = i >> 6, f = i & 63;
        Ws[i] = Wout[f * H_ + j];
    }
    if (threadIdx.x < F_) bs[threadIdx.x] = bout[threadIdx.x];
    __syncthreads();

    const int b  = threadIdx.x & 127;
    const int fg = (threadIdx.x >> 7) * 32;     // f-group: 0 or 32

    u64 acc[16];                                // pairs (fg+2i, fg+2i+1)
    #pragma unroll
    for (int i = 0; i < 16; ++i) acc[i] = pack2(bs[fg + 2 * i], bs[fg + 2 * i + 1]);

    const float* hrow = d_hist + (size_t)s * (H_ * B_) + b;
    #pragma unroll 8
    for (int j = 0; j < H_; ++j) {
        float hv = __ldcs(hrow + (size_t)j * B_);    // streaming: hist read once
        u64 hh = pack2(hv, hv);
        const ulonglong2* wr = (const ulonglong2*)(Ws + j * F_ + fg);
        #pragma unroll
        for (int i = 0; i < 8; ++i) {
            ulonglong2 wv = wr[i];
            fma2(acc[2 * i],     hh, wv.x);
            fma2(acc[2 * i + 1], hh, wv.y);
        }
    }

    float* orow = out + (size_t)b * (T_ * F_) + t * F_ + fg;
    #pragma unroll
    for (int i = 0; i < 16; ++i) {
        float lo, hi; unpack2(lo, hi, acc[i]);
        *(float2*)(orow + 2 * i) = make_float2(lo, hi);
    }
}

// ---------------- launch ----------------
extern "C" void kernel_launch(void* const* d_in, const int* in_sizes, int n_in,
                              void* d_out, int out_size) {
    const float* ts    = (const float*)d_in[0];
    const float* Wih_e = (const float*)d_in[1];
    const float* Whh_e = (const float*)d_in[2];
    const float* b_e   = (const float*)d_in[3];
    const float* Wih_d = (const float*)d_in[4];
    const float* Whh_d = (const float*)d_in[5];
    const float* b_d   = (const float*)d_in[6];
    const float* Wout  = (const float*)d_in[7];
    const float* bout  = (const float*)d_in[8];
    float* out = (float*)d_out;

    cudaFuncSetAttribute(lstm_persistent, cudaFuncAttributeMaxDynamicSharedMemorySize,
                         SMEM_PERSIST_BYTES);
    cudaFuncSetAttribute(proj_kernel, cudaFuncAttributeMaxDynamicSharedMemorySize,
                         SMEM_PROJ_BYTES);

    init_kernel<<<128, 256>>>();
    transpose_kernel<<<T_, NTHR>>>(ts);
    lstm_persistent<<<NCTA, NTHR, SMEM_PERSIST_BYTES>>>(Wih_e, Whh_e, b_e,
                                                        Wih_d, Whh_d, b_d);
    proj_kernel<<<T_, 256, SMEM_PROJ_BYTES>>>(Wout, bout, out);
}

// round 12
// speedup vs baseline: 1.2305x; 1.0294x over previous
#include <cuda_runtime.h>
#include <cuda_bf16.h>

#define B_   128
#define T_   1024
#define F_   64
#define H_   256
#define KTOT 320           // F + H
#define NCTA 128
#define NTHR 256

typedef unsigned long long u64;

// ---------------- packed f32x2 helpers (sm_103a FFMA2 path) ----------------
__device__ __forceinline__ u64 pack2(float x, float y) {
    u64 r; asm("mov.b64 %0, {%1,%2};" : "=l"(r) : "f"(x), "f"(y)); return r;
}
__device__ __forceinline__ void fma2(u64& d, u64 a, u64 b) {
    asm("fma.rn.f32x2 %0, %1, %2, %0;" : "+l"(d) : "l"(a), "l"(b));
}
__device__ __forceinline__ void unpack2(float& x, float& y, u64 v) {
    asm("mov.b64 {%0,%1}, %2;" : "=f"(x), "=f"(y) : "l"(v));
}

// ---------------- static device scratch (no runtime allocs) ----------------
__device__ float d_xT[T_ * F_ * B_];        // [t][f][b]       33.5 MB
__device__ float d_hist[T_ * H_ * B_];      // [s][j][b]      134.2 MB (decoder carry h)
__device__ float d_H[2 * H_ * B_];          // double-buffered h, [buf][j][b]
__device__ unsigned d_bar4[128];            // 4 group-barrier counters, stride 128B

// ---------------- kernel 0: reset barriers + zero h0 ----------------
__global__ void init_kernel() {
    int i = blockIdx.x * blockDim.x + threadIdx.x;   // 32768 = H_*B_
    d_H[i] = 0.0f;                                   // buffer 0 = initial h = 0
    if (i < 128) d_bar4[i] = 0u;
}

// ---------------- no-op kernel: pads launch sequence so ncu -s 5 profiles lstm ----------------
__global__ void nop_kernel() {}

// ---------------- kernel 1: transpose x to [t][f][b] ----------------
__global__ __launch_bounds__(NTHR) void transpose_kernel(const float* __restrict__ ts) {
    __shared__ float tile[F_][B_ + 1];
    int t = blockIdx.x;
    for (int idx = threadIdx.x; idx < B_ * F_; idx += NTHR) {
        int b = idx >> 6, f = idx & 63;
        tile[f][b] = ts[(size_t)b * (T_ * F_) + t * F_ + f];     // coalesced over f
    }
    __syncthreads();
    for (int idx = threadIdx.x; idx < F_ * B_; idx += NTHR) {
        int f = idx >> 7, b = idx & 127;
        d_xT[(size_t)t * (F_ * B_) + f * B_ + b] = tile[f][b];   // coalesced over b
    }
}

// ---------------- kernel 2: persistent LSTM (encoder + decoder) ----------------
// smem floats: Ah[256][32]=8192 | xbuf[2][64][32]=4096 | W[2][320][32]=20480 | stg[2][32][33]=2112
#define SM_AH_OFF  0
#define SM_XB_OFF  8192
#define SM_W_OFF   12288
#define SM_S_OFF   32768
#define SMEM_PERSIST_FLOATS (32768 + 2112)
#define SMEM_PERSIST_BYTES  (SMEM_PERSIST_FLOATS * 4)

__device__ __forceinline__ float sigf(float x) { return 1.0f / (1.0f + __expf(-x)); }

__global__ void __launch_bounds__(NTHR, 1) lstm_persistent(
    const float* __restrict__ Wih_e, const float* __restrict__ Whh_e, const float* __restrict__ b_e,
    const float* __restrict__ Wih_d, const float* __restrict__ Whh_d, const float* __restrict__ b_d)
{
    extern __shared__ float sm[];
    float* Ah   = sm + SM_AH_OFF;           // h operand [j=0..255][32 b]
    float* Xb   = sm + SM_XB_OFF;           // x operand double buffer [2][64][32]
    float* W    = sm + SM_W_OFF;
    float* stg0 = sm + SM_S_OFF;
    float* stg1 = stg0 + 32 * 33;

    const int tid = threadIdx.x;
    const int cta = blockIdx.x;
    const int ms  = cta >> 5;          // 0..3  : 32-batch slice (independent barrier group)
    const int ns  = cta & 31;          // 0..31 : 8-hidden-unit slice
    const int m0  = ms * 32;
    unsigned* barp = &d_bar4[ms * 32];

    // Split-K GEMM coords: 16x8 thread grid per group, 2x4 register tile
    const int gid  = tid >> 7;         // 0/1 : K-group
    const int half = tid & 127;
    const int tx   = half & 7;         // n-quad:  n0 = 4*tx
    const int ty   = half >> 3;        // m-pair:  mm = 2*ty
    const int xk0  = gid * 32;         // x-part: 32 k each (of 64)
    const int hk0  = gid * 128;        // h-part: 128 k each (of 256)
    float* stgW = gid ? stg1 : stg0;

    // update/IO coords
    const int jl = tid >> 5;           // 0..7  local hidden unit
    const int mu = tid & 31;           // 0..31 local batch row
    const int jg = ns * 8 + jl;        // global hidden unit

    // ---- load both phases' weight slices into smem (once) ----
    // W[p][k][n]; column n -> gate g = n>>3, hidden j = ns*8+(n&7); weight row = g*H + j
    for (int idx = tid; idx < 2 * KTOT * 32; idx += NTHR) {
        int p = idx / (KTOT * 32);
        int r = idx - p * (KTOT * 32);
        int k = r >> 5, n = r & 31;
        int row = (n >> 3) * H_ + (ns * 8 + (n & 7));
        const float* Wih = p ? Wih_d : Wih_e;
        const float* Whh = p ? Whh_d : Whh_e;
        W[idx] = (k < F_) ? Wih[row * F_ + k] : Whh[row * H_ + (k - F_)];
    }

    // biases
    const float bie = b_e[0 * H_ + jg], bfe = b_e[1 * H_ + jg],
                bge = b_e[2 * H_ + jg], boe = b_e[3 * H_ + jg];
    const float bid = b_d[0 * H_ + jg], bfd = b_d[1 * H_ + jg],
                bgd = b_d[2 * H_ + jg], bod = b_d[3 * H_ + jg];

    float4* Xv = (float4*)Xb;

    // ---- prologue: stage x(0) into xbuf[0] ----
    {
        const float4* xsrc = (const float4*)(d_xT + m0);   // t = 0
        #pragma unroll
        for (int u = 0; u < 2; ++u) {
            int i = tid + u * NTHR;                         // [0,512)
            int r = i >> 3, q = i & 7;
            Xv[r * 8 + q] = __ldg(xsrc + r * (B_ / 4) + q);
        }
    }
    __syncthreads();   // weights + x0 ready

    // ---- prologue: acc = x-part(step 0) from xbuf[0] ----
    u64 c00 = 0ull, c01 = 0ull, c10 = 0ull, c11 = 0ull;
    {
        const float* Xp = Xb + 2 * ty;          // xbuf[0]
        const float* Bp = W + 4 * tx;           // encoder, x rows (k<64)
        #pragma unroll 8
        for (int kk = 0; kk < 32; ++kk) {
            int k = xk0 + kk;
            float2 av = *(const float2*)(Xp + k * 32);
            ulonglong2 bb = *(const ulonglong2*)(Bp + k * 32);
            u64 a0 = pack2(av.x, av.x);
            u64 a1 = pack2(av.y, av.y);
            fma2(c00, a0, bb.x); fma2(c01, a0, bb.y);
            fma2(c10, a1, bb.x); fma2(c11, a1, bb.y);
        }
    }
    // ---- prologue: prefetch x(1) into xbuf[1] ----
    {
        const float4* xs2 = (const float4*)(d_xT + (size_t)1 * (F_ * B_) + m0);
        #pragma unroll
        for (int u = 0; u < 2; ++u) {
            int i = tid + u * NTHR;
            int r = i >> 3, q = i & 7;
            Xv[512 + r * 8 + q] = __ldg(xs2 + r * (B_ / 4) + q);
        }
    }

    float c_reg = 0.0f;

    for (int step = 0; step < 2 * T_; ++step) {
        const bool dec = (step >= T_);
        const float* Wp = W + (dec ? KTOT * 32 : 0);

        // ---- 1. wait for h(step): all group CTAs finished iteration step-1 ----
        if (tid == 0) {
            const unsigned target = (unsigned)step * 32u;
            unsigned v;
            do {
                asm volatile("ld.acquire.gpu.global.u32 %0, [%1];"
                             : "=r"(v) : "l"(barp) : "memory");
            } while (v < target);
        }
        __syncthreads();

        // ---- 2. load h(step) from d_H[step&1] ----
        float4 hreg[8];
        {
            const float4* hsrc = (const float4*)(d_H + (step & 1) * (H_ * B_) + m0);
            #pragma unroll
            for (int u = 0; u < 8; ++u) {
                int i = tid + u * NTHR;
                int r = i >> 3, q = i & 7;
                hreg[u] = __ldcg(hsrc + r * (B_ / 4) + q);
            }
        }
        // ---- 3. store h into smem Ah ----
        {
            float4* Av = (float4*)Ah;
            #pragma unroll
            for (int u = 0; u < 8; ++u) {
                int i = tid + u * NTHR;
                int r = i >> 3, q = i & 7;
                Av[r * 8 + q] = hreg[u];
            }
        }
        __syncthreads();

        // ---- 4. h-part GEMM (128 k per group) ----
        {
            const float* Ap = Ah + 2 * ty;
            const float* Bp = Wp + (F_ * 32) + 4 * tx;     // h rows start at k=64
            #pragma unroll 8
            for (int kk = 0; kk < 128; ++kk) {
                int k = hk0 + kk;
                float2 av = *(const float2*)(Ap + k * 32);
                ulonglong2 bb = *(const ulonglong2*)(Bp + k * 32);
                u64 a0 = pack2(av.x, av.x);
                u64 a1 = pack2(av.y, av.y);
                fma2(c00, a0, bb.x); fma2(c01, a0, bb.y);
                fma2(c10, a1, bb.x); fma2(c11, a1, bb.y);
            }
        }

        // ---- 5. write gate partials ----
        {
            float v0, v1, v2, v3;
            float* r0 = stgW + (2 * ty)     * 33 + 4 * tx;
            float* r1 = stgW + (2 * ty + 1) * 33 + 4 * tx;
            unpack2(v0, v1, c00); unpack2(v2, v3, c01);
            r0[0] = v0; r0[1] = v1; r0[2] = v2; r0[3] = v3;
            unpack2(v0, v1, c10); unpack2(v2, v3, c11);
            r1[0] = v0; r1[1] = v1; r1[2] = v2; r1[3] = v3;
        }
        __syncthreads();

        // ---- 6. activations + cell update for (mu, jl) ----
        float gi = stg0[mu * 33 +      jl] + stg1[mu * 33 +      jl] + (dec ? bid : bie);
        float gf = stg0[mu * 33 +  8 + jl] + stg1[mu * 33 +  8 + jl] + (dec ? bfd : bfe);
        float gg = stg0[mu * 33 + 16 + jl] + stg1[mu * 33 + 16 + jl] + (dec ? bgd : bge);
        float go = stg0[mu * 33 + 24 + jl] + stg1[mu * 33 + 24 + jl] + (dec ? bod : boe);
        gi = sigf(gi); gf = sigf(gf); go = sigf(go);
        gg = tanhf(gg);
        c_reg = gf * c_reg + gi * gg;
        float h = go * tanhf(c_reg);

        __stcg(d_H + ((step + 1) & 1) * (H_ * B_) + jg * B_ + m0 + mu, h);

        // ---- 7. arrive (release: h store above is ordered-before via bar + red.release) ----
        __syncthreads();
        if (tid == 0) {
            asm volatile("red.release.gpu.global.add.u32 [%0], 1;"
                         :: "l"(barp) : "memory");
        }

        // ======== post-arrive window: overlapped with other CTAs' catch-up ========

        // ---- 8. decoder-carry history (off other CTAs' critical path) ----
        if (step >= T_ - 1 && step < 2 * T_ - 1) {
            int s = step - (T_ - 1);
            d_hist[(size_t)s * (H_ * B_) + jg * B_ + m0 + mu] = h;
        }

        // ---- 9. x-part GEMM for step+1 from xbuf[(step+1)&1] → new acc ----
        if (step + 1 < 2 * T_) {
            const bool decn = (step + 1 >= T_);
            const float* Wpn = W + (decn ? KTOT * 32 : 0);
            const float* Xp  = Xb + ((step + 1) & 1) * (64 * 32) + 2 * ty;
            const float* Bp  = Wpn + 4 * tx;
            c00 = 0ull; c01 = 0ull; c10 = 0ull; c11 = 0ull;
            #pragma unroll 8
            for (int kk = 0; kk < 32; ++kk) {
                int k = xk0 + kk;
                float2 av = *(const float2*)(Xp + k * 32);
                ulonglong2 bb = *(const ulonglong2*)(Bp + k * 32);
                u64 a0 = pack2(av.x, av.x);
                u64 a1 = pack2(av.y, av.y);
                fma2(c00, a0, bb.x); fma2(c01, a0, bb.y);
                fma2(c10, a1, bb.x); fma2(c11, a1, bb.y);
            }
        }

        // ---- 10. prefetch x(step+2) into xbuf[(step+2)&1] = xbuf[step&1] ----
        if (step + 2 < 2 * T_) {
            const int sn = step + 2;
            const int tn = (sn >= T_) ? (2 * T_ - 1 - sn) : sn;
            const float4* xs2 = (const float4*)(d_xT + (size_t)tn * (F_ * B_) + m0);
            float4* dst = Xv + (step & 1) * 512;
            #pragma unroll
            for (int u = 0; u < 2; ++u) {
                int i = tid + u * NTHR;
                int r = i >> 3, q = i & 7;
                dst[r * 8 + q] = __ldg(xs2 + r * (B_ / 4) + q);
            }
        }
    }
}

// ---------------- kernel 3: output projection (f32x2) ----------------
// out[b][t][f] = sum_j hist[T-1-t][j][b] * W_out[f][j] + b_out[f]
#define SMEM_PROJ_BYTES ((H_ * F_ + F_) * 4)

__global__ void __launch_bounds__(256) proj_kernel(
    const float* __restrict__ Wout, const float* __restrict__ bout, float* __restrict__ out)
{
    extern __shared__ float sm[];
    float* Ws = sm;              // [j][f] transposed W_out
    float* bs = sm + H_ * F_;

    const int t = blockIdx.x;
    const int s = T_ - 1 - t;
    for (int i = threadIdx.x; i < H_ * F_; i += 256) {
        int j = i >> 6, f = i & 63;
        Ws[i] = Wout[f * H_ + j];
    }
    if (threadIdx.x < F_) bs[threadIdx.x] = bout[threadIdx.x];
    __syncthreads();

    const int b  = threadIdx.x & 127;
    const int fg = (threadIdx.x >> 7) * 32;     // f-group: 0 or 32

    u64 acc[16];                                // pairs (fg+2i, fg+2i+1)
    #pragma unroll
    for (int i = 0; i < 16; ++i) acc[i] = pack2(bs[fg + 2 * i], bs[fg + 2 * i + 1]);

    const float* hrow = d_hist + (size_t)s * (H_ * B_) + b;
    #pragma unroll 8
    for (int j = 0; j < H_; ++j) {
        float hv = __ldcs(hrow + (size_t)j * B_);    // streaming: hist read once
        u64 hh = pack2(hv, hv);
        const ulonglong2* wr = (const ulonglong2*)(Ws + j * F_ + fg);
        #pragma unroll
        for (int i = 0; i < 8; ++i) {
            ulonglong2 wv = wr[i];
            fma2(acc[2 * i],     hh, wv.x);
            fma2(acc[2 * i + 1], hh, wv.y);
        }
    }

    float* orow = out + (size_t)b * (T_ * F_) + t * F_ + fg;
    #pragma unroll
    for (int i = 0; i < 16; ++i) {
        float lo, hi; unpack2(lo, hi, acc[i]);
        *(float2*)(orow + 2 * i) = make_float2(lo, hi);
    }
}

// ---------------- launch ----------------
extern "C" void kernel_launch(void* const* d_in, const int* in_sizes, int n_in,
                              void* d_out, int out_size) {
    const float* ts    = (const float*)d_in[0];
    const float* Wih_e = (const float*)d_in[1];
    const float* Whh_e = (const float*)d_in[2];
    const float* b_e   = (const float*)d_in[3];
    const float* Wih_d = (const float*)d_in[4];
    const float* Whh_d = (const float*)d_in[5];
    const float* b_d   = (const float*)d_in[6];
    const float* Wout  = (const float*)d_in[7];
    const float* bout  = (const float*)d_in[8];
    float* out = (float*)d_out;

    cudaFuncSetAttribute(lstm_persistent, cudaFuncAttributeMaxDynamicSharedMemorySize,
                         SMEM_PERSIST_BYTES);
    cudaFuncSetAttribute(proj_kernel, cudaFuncAttributeMaxDynamicSharedMemorySize,
                         SMEM_PROJ_BYTES);

    init_kernel<<<128, 256>>>();          // launch 0
    transpose_kernel<<<T_, NTHR>>>(ts);   // launch 1
    nop_kernel<<<1, 32>>>();              // launch 2 ─┐ pad so lstm is launch #5,
    nop_kernel<<<1, 32>>>();              // launch 3  │ where ncu -s 5 -c 1 samples
    nop_kernel<<<1, 32>>>();              // launch 4 ─┘
    lstm_persistent<<<NCTA, NTHR, SMEM_PERSIST_BYTES>>>(Wih_e, Whh_e, b_e,   // launch 5
                                                        Wih_d, Whh_d, b_d);
    proj_kernel<<<T_, 256, SMEM_PROJ_BYTES>>>(Wout, bout, out);              // launch 6
}